// round 3
// baseline (speedup 1.0000x reference)
#include <cuda_runtime.h>
#include <cuda_bf16.h>
#include <cstdint>

// VDP dropout: keep = (u >= 0.1)
//   mu_out    = mu_in    * keep / 0.9
//   Sigma_out = Sigma_in * keep / 768
// Pure streaming elementwise; HBM-bound. float4 vectorized, 4 float4/thread
// for MLP, streaming cache hints (no reuse; 194MB working set > L2).

static constexpr float DROP_PROP = 0.1f;
static constexpr float INV_KEEP  = 1.0f / (1.0f - DROP_PROP);   // 1/0.9
static constexpr float INV_D     = 1.0f / 768.0f;

static constexpr int VPT = 4;   // float4s per thread

__global__ void __launch_bounds__(256)
vdp_dropout_kernel(const float4* __restrict__ mu,
                   const float4* __restrict__ sigma,
                   const float4* __restrict__ u,
                   float4* __restrict__ mu_out,
                   float4* __restrict__ sigma_out,
                   int n4)
{
    // Block-strided: each block owns a contiguous chunk of VPT*blockDim
    // float4s; iteration j touches a contiguous 16KB slab (fully coalesced).
    int base = blockIdx.x * (blockDim.x * VPT) + threadIdx.x;

    if (base + (VPT - 1) * blockDim.x < n4) {
        // Fast path: full block, no predication — 12 front-batched LDG.128.
        float4 m[VPT], s[VPT], r[VPT];
#pragma unroll
        for (int j = 0; j < VPT; j++) {
            int idx = base + j * blockDim.x;
            m[j] = __ldcs(mu + idx);
            s[j] = __ldcs(sigma + idx);
            r[j] = __ldcs(u + idx);
        }
#pragma unroll
        for (int j = 0; j < VPT; j++) {
            float4 mo, so;
            mo.x = (r[j].x >= DROP_PROP) ? m[j].x * INV_KEEP : 0.0f;
            mo.y = (r[j].y >= DROP_PROP) ? m[j].y * INV_KEEP : 0.0f;
            mo.z = (r[j].z >= DROP_PROP) ? m[j].z * INV_KEEP : 0.0f;
            mo.w = (r[j].w >= DROP_PROP) ? m[j].w * INV_KEEP : 0.0f;
            so.x = (r[j].x >= DROP_PROP) ? s[j].x * INV_D : 0.0f;
            so.y = (r[j].y >= DROP_PROP) ? s[j].y * INV_D : 0.0f;
            so.z = (r[j].z >= DROP_PROP) ? s[j].z * INV_D : 0.0f;
            so.w = (r[j].w >= DROP_PROP) ? s[j].w * INV_D : 0.0f;
            int idx = base + j * blockDim.x;
            __stcs(mu_out + idx, mo);
            __stcs(sigma_out + idx, so);
        }
    } else {
        // Tail path: per-element guard.
#pragma unroll
        for (int j = 0; j < VPT; j++) {
            int idx = base + j * blockDim.x;
            if (idx >= n4) continue;
            float4 m = __ldcs(mu + idx);
            float4 s = __ldcs(sigma + idx);
            float4 r = __ldcs(u + idx);
            float4 mo, so;
            mo.x = (r.x >= DROP_PROP) ? m.x * INV_KEEP : 0.0f;
            mo.y = (r.y >= DROP_PROP) ? m.y * INV_KEEP : 0.0f;
            mo.z = (r.z >= DROP_PROP) ? m.z * INV_KEEP : 0.0f;
            mo.w = (r.w >= DROP_PROP) ? m.w * INV_KEEP : 0.0f;
            so.x = (r.x >= DROP_PROP) ? s.x * INV_D : 0.0f;
            so.y = (r.y >= DROP_PROP) ? s.y * INV_D : 0.0f;
            so.z = (r.z >= DROP_PROP) ? s.z * INV_D : 0.0f;
            so.w = (r.w >= DROP_PROP) ? s.w * INV_D : 0.0f;
            __stcs(mu_out + idx, mo);
            __stcs(sigma_out + idx, so);
        }
    }
}

extern "C" void kernel_launch(void* const* d_in, const int* in_sizes, int n_in,
                              void* d_out, int out_size)
{
    const float* mu    = (const float*)d_in[0];
    const float* sigma = (const float*)d_in[1];
    const float* u     = (const float*)d_in[2];
    float* out = (float*)d_out;

    int n = in_sizes[0];            // 9,683,456 elements
    int n4 = n / 4;                 // 2,420,864 float4s

    float* mu_out    = out;         // outputs concatenated: (mu_out, Sigma_out)
    float* sigma_out = out + n;

    int threads = 256;
    int per_block = threads * VPT;
    int blocks = (n4 + per_block - 1) / per_block;   // 2364
    vdp_dropout_kernel<<<blocks, threads>>>(
        (const float4*)mu, (const float4*)sigma, (const float4*)u,
        (float4*)mu_out, (float4*)sigma_out, n4);
}

// round 4
// speedup vs baseline: 1.0010x; 1.0010x over previous
#include <cuda_runtime.h>
#include <cuda_bf16.h>
#include <cstdint>

// VDP dropout: keep = (u >= 0.1)
//   mu_out    = mu_in    * keep / 0.9
//   Sigma_out = Sigma_in * keep / 768
//
// Pure streaming elementwise; HBM-bound. R1 shape (1 float4/thread, MLP_p1=3
// — avoids the cross-CTA L1tex spread regime measured in R3). Loads use the
// DEFAULT cache policy so inputs stay L2-resident across graph replays
// (~48MB/replay hit in L2 in R1); stores use .cs (evict-first) since the
// output is write-once/never-read and should not displace input lines.

static constexpr float DROP_PROP = 0.1f;
static constexpr float INV_KEEP  = 1.0f / (1.0f - DROP_PROP);   // 1/0.9
static constexpr float INV_D     = 1.0f / 768.0f;

__global__ void __launch_bounds__(256)
vdp_dropout_kernel(const float4* __restrict__ mu,
                   const float4* __restrict__ sigma,
                   const float4* __restrict__ u,
                   float4* __restrict__ mu_out,
                   float4* __restrict__ sigma_out,
                   int n4)
{
    int i = blockIdx.x * blockDim.x + threadIdx.x;
    if (i >= n4) return;

    // Default-policy loads: keep inputs L2-resident across replays.
    float4 m = mu[i];
    float4 s = sigma[i];
    float4 r = u[i];

    float4 mo, so;
    mo.x = (r.x >= DROP_PROP) ? m.x * INV_KEEP : 0.0f;
    mo.y = (r.y >= DROP_PROP) ? m.y * INV_KEEP : 0.0f;
    mo.z = (r.z >= DROP_PROP) ? m.z * INV_KEEP : 0.0f;
    mo.w = (r.w >= DROP_PROP) ? m.w * INV_KEEP : 0.0f;
    so.x = (r.x >= DROP_PROP) ? s.x * INV_D : 0.0f;
    so.y = (r.y >= DROP_PROP) ? s.y * INV_D : 0.0f;
    so.z = (r.z >= DROP_PROP) ? s.z * INV_D : 0.0f;
    so.w = (r.w >= DROP_PROP) ? s.w * INV_D : 0.0f;

    // Evict-first stores: output is never read; don't pollute L2.
    __stcs(mu_out + i, mo);
    __stcs(sigma_out + i, so);
}

extern "C" void kernel_launch(void* const* d_in, const int* in_sizes, int n_in,
                              void* d_out, int out_size)
{
    const float* mu    = (const float*)d_in[0];
    const float* sigma = (const float*)d_in[1];
    const float* u     = (const float*)d_in[2];
    float* out = (float*)d_out;

    int n = in_sizes[0];            // 9,683,456 elements
    int n4 = n / 4;                 // 2,420,864 float4s

    float* mu_out    = out;         // outputs concatenated: (mu_out, Sigma_out)
    float* sigma_out = out + n;

    int threads = 256;
    int blocks = (n4 + threads - 1) / threads;   // 9457
    vdp_dropout_kernel<<<blocks, threads>>>(
        (const float4*)mu, (const float4*)sigma, (const float4*)u,
        (float4*)mu_out, (float4*)sigma_out, n4);
}

// round 6
// speedup vs baseline: 1.0067x; 1.0058x over previous
#include <cuda_runtime.h>
#include <cuda_bf16.h>
#include <cstdint>

// VDP dropout: keep = (u >= 0.1)
//   mu_out    = mu_in    * keep / 0.9
//   Sigma_out = Sigma_in * keep / 768
//
// Pure streaming elementwise at the HBM roofline (R1/R4 measured 7.9 TB/s
// effective = ~99% of spec; 193.7 MB irreducible traffic). This round: exact
// one-wave persistent grid (152 SMs x 8 CTAs) with a grid-stride loop to
// eliminate multi-wave CTA dispatch; default cache policy throughout
// (matches best-measured R1; .cs variants were neutral-to-negative).

static constexpr float DROP_PROP = 0.1f;
static constexpr float INV_KEEP  = 1.0f / (1.0f - DROP_PROP);   // 1/0.9
static constexpr float INV_D     = 1.0f / 768.0f;

__global__ void __launch_bounds__(256)
vdp_dropout_kernel(const float4* __restrict__ mu,
                   const float4* __restrict__ sigma,
                   const float4* __restrict__ u,
                   float4* __restrict__ mu_out,
                   float4* __restrict__ sigma_out,
                   int n4)
{
    int stride = gridDim.x * blockDim.x;
    for (int i = blockIdx.x * blockDim.x + threadIdx.x; i < n4; i += stride) {
        float4 m = mu[i];
        float4 s = sigma[i];
        float4 r = u[i];

        float4 mo, so;
        mo.x = (r.x >= DROP_PROP) ? m.x * INV_KEEP : 0.0f;
        mo.y = (r.y >= DROP_PROP) ? m.y * INV_KEEP : 0.0f;
        mo.z = (r.z >= DROP_PROP) ? m.z * INV_KEEP : 0.0f;
        mo.w = (r.w >= DROP_PROP) ? m.w * INV_KEEP : 0.0f;
        so.x = (r.x >= DROP_PROP) ? s.x * INV_D : 0.0f;
        so.y = (r.y >= DROP_PROP) ? s.y * INV_D : 0.0f;
        so.z = (r.z >= DROP_PROP) ? s.z * INV_D : 0.0f;
        so.w = (r.w >= DROP_PROP) ? s.w * INV_D : 0.0f;

        mu_out[i]    = mo;
        sigma_out[i] = so;
    }
}

extern "C" void kernel_launch(void* const* d_in, const int* in_sizes, int n_in,
                              void* d_out, int out_size)
{
    const float* mu    = (const float*)d_in[0];
    const float* sigma = (const float*)d_in[1];
    const float* u     = (const float*)d_in[2];
    float* out = (float*)d_out;

    int n = in_sizes[0];            // 9,683,456 elements
    int n4 = n / 4;                 // 2,420,864 float4s

    float* mu_out    = out;         // outputs concatenated: (mu_out, Sigma_out)
    float* sigma_out = out + n;

    // One full wave: 152 SMs on GB300, 8 CTAs/SM at 256 thr (2048 thr/SM cap).
    int threads = 256;
    int blocks = 152 * 8;           // 1216 CTAs, grid-stride covers n4
    vdp_dropout_kernel<<<blocks, threads>>>(
        (const float4*)mu, (const float4*)sigma, (const float4*)u,
        (float4*)mu_out, (float4*)sigma_out, n4);
}